// round 10
// baseline (speedup 1.0000x reference)
#include <cuda_runtime.h>
#include <cuda_bf16.h>
#include <mma.h>
#include <cstdint>

using namespace nvcuda;

// ============================================================================
// DETRsmpl head, HMMA bf16 3-term split, sm_103 base.
// R10 = R9 with the splitstore4 identifier typo fixed.
// NT=256, 2 CTAs/SM, 2m x 4n warp tiles, Hsum in global scratch, grid 296.
//   u0 = x@W1a ; h_i = relu(u_i + c1 + i*cvec) ; u_{i+1} = u_i + h_i@W231
//   theta = (theta0 + 3 b23) + (h0+h1+h2)@W23
// ============================================================================

#define NT 256
#define MR 64
#define HLD 264      // H/A panel stride (bf16)
#define BLD 264      // B chunk stride (bf16)
#define THLD 164     // theta f32 stride (aliases H region)
#define NGRID 296
#define NTILE 1800

// smem layout (bytes)
#define OFF_H    0        // Hh 33792 | Hl 33792
#define OFF_B    67584    // 2 slots x 16896 (hi 8448 | lo 8448)
#define OFF_SCR  101376   // 8 warps x 1KB
#define OFF_SB   109568   // bias 256 f32
#define SMEM_SZ  110592

__device__ __nv_bfloat16 g_W1h[256 * 256];    // W1a split
__device__ __nv_bfloat16 g_W1l[256 * 256];
__device__ __nv_bfloat16 g_W231h[256 * 256];  // (W2@W3@W1b) split
__device__ __nv_bfloat16 g_W231l[256 * 256];
__device__ __nv_bfloat16 g_W23h[256 * 192];   // (W2@W3) split, N pad 192
__device__ __nv_bfloat16 g_W23l[256 * 192];
__device__ float g_W23p[256 * 192];
__device__ float g_c1[256];
__device__ float g_cb[3 * 256];               // bias_i = c1 + i*cvec
__device__ float g_b23[160];
__device__ float g_tfin[160];                 // theta0 + 3*b23
__device__ float g_Hs[NGRID * MR * 256];      // per-CTA hsum scratch

// ---------------- helpers ----------------
#define CP16(dst, src) asm volatile("cp.async.cg.shared.global [%0], [%1], 16;" :: "r"(dst), "l"(src))
#define CP_COMMIT()    asm volatile("cp.async.commit_group;" ::: "memory")
#define CP_WAIT0()     asm volatile("cp.async.wait_group 0;" ::: "memory")

__device__ __forceinline__ uint32_t pk2(__nv_bfloat16 a, __nv_bfloat16 b) {
    return (uint32_t)__bfloat16_as_ushort(a) | ((uint32_t)__bfloat16_as_ushort(b) << 16);
}

__device__ __forceinline__ void splitstore4(__nv_bfloat16* ph, __nv_bfloat16* pl, float4 v) {
    __nv_bfloat16 h0 = __float2bfloat16(v.x), h1 = __float2bfloat16(v.y);
    __nv_bfloat16 h2 = __float2bfloat16(v.z), h3 = __float2bfloat16(v.w);
    __nv_bfloat16 l0 = __float2bfloat16(v.x - __bfloat162float(h0));
    __nv_bfloat16 l1 = __float2bfloat16(v.y - __bfloat162float(h1));
    __nv_bfloat16 l2 = __float2bfloat16(v.z - __bfloat162float(h2));
    __nv_bfloat16 l3 = __float2bfloat16(v.w - __bfloat162float(h3));
    *reinterpret_cast<uint2*>(ph) = make_uint2(pk2(h0, h1), pk2(h2, h3));
    *reinterpret_cast<uint2*>(pl) = make_uint2(pk2(l0, l1), pk2(l2, l3));
}

// ---------------- prep kernels ----------------
__global__ void prep1_k(const float* __restrict__ W1, const float* __restrict__ b1,
                        const float* __restrict__ W2, const float* __restrict__ b2,
                        const float* __restrict__ W3, const float* __restrict__ b3,
                        const float* __restrict__ icr, const float* __restrict__ ish,
                        const float* __restrict__ icam) {
    __shared__ float sth[160];
    int b = blockIdx.x, t = threadIdx.x;
    if (b < 256) {
        float v = W1[b * 256 + t];
        __nv_bfloat16 h = __float2bfloat16(v);
        __nv_bfloat16 l = __float2bfloat16(v - __bfloat162float(h));
        g_W1h[b * 256 + t] = h;
        g_W1l[b * 256 + t] = l;
    } else if (b < 512) {
        int k = b - 256;
        if (t < 192) {
            float s0 = 0, s1 = 0, s2 = 0, s3 = 0;
            if (t < 157) {
                for (int m = 0; m < 256; m += 4) {
                    s0 = fmaf(W2[k * 256 + m + 0], W3[(m + 0) * 157 + t], s0);
                    s1 = fmaf(W2[k * 256 + m + 1], W3[(m + 1) * 157 + t], s1);
                    s2 = fmaf(W2[k * 256 + m + 2], W3[(m + 2) * 157 + t], s2);
                    s3 = fmaf(W2[k * 256 + m + 3], W3[(m + 3) * 157 + t], s3);
                }
            }
            float v = (s0 + s1) + (s2 + s3);
            g_W23p[k * 192 + t] = v;
            __nv_bfloat16 h = __float2bfloat16(v);
            __nv_bfloat16 l = __float2bfloat16(v - __bfloat162float(h));
            g_W23h[k * 192 + t] = h;
            g_W23l[k * 192 + t] = l;
        }
    } else if (b == 512) {
        if (t < 160) {
            float v = 0.f;
            if (t < 144) v = icr[t];
            else if (t < 154) v = ish[t - 144];
            else if (t < 157) v = icam[t - 154];
            sth[t] = v;
        }
        __syncthreads();
        float s = b1[t];
        for (int k = 0; k < 157; k++)
            s = fmaf(sth[k], W1[(256 + k) * 256 + t], s);
        g_c1[t] = s;
    } else {
        if (t < 160) {
            float s = 0.f;
            if (t < 157) {
                s = b3[t];
                for (int m = 0; m < 256; m++)
                    s = fmaf(b2[m], W3[m * 157 + t], s);
            }
            g_b23[t] = s;
            float v = 0.f;
            if (t < 144) v = icr[t];
            else if (t < 154) v = ish[t - 144];
            else if (t < 157) v = icam[t - 154];
            g_tfin[t] = v + 3.f * s;
        }
    }
}

__global__ void prep2_k(const float* __restrict__ W1) {
    int b = blockIdx.x, t = threadIdx.x;
    if (b < 256) {
        float s = 0.f;
        for (int k = 0; k < 157; k++)
            s = fmaf(g_W23p[b * 192 + k], W1[(256 + k) * 256 + t], s);
        __nv_bfloat16 h = __float2bfloat16(s);
        __nv_bfloat16 l = __float2bfloat16(s - __bfloat162float(h));
        g_W231h[b * 256 + t] = h;
        g_W231l[b * 256 + t] = l;
    } else {
        float cv = 0.f;
        for (int k = 0; k < 157; k++)
            cv = fmaf(g_b23[k], W1[(256 + k) * 256 + t], cv);
        float c1 = g_c1[t];
        g_cb[0 * 256 + t] = c1;
        g_cb[1 * 256 + t] = c1 + cv;
        g_cb[2 * 256 + t] = c1 + 2.f * cv;
    }
}

// ---------------- main kernel ----------------
typedef wmma::fragment<wmma::matrix_a, 16, 16, 16, __nv_bfloat16, wmma::row_major> FragA;
typedef wmma::fragment<wmma::matrix_b, 16, 16, 16, __nv_bfloat16, wmma::row_major> FragB;
typedef wmma::fragment<wmma::accumulator, 16, 16, 16, float> FragC;

__global__ __launch_bounds__(NT, 2)
void detr_wmma(const float* __restrict__ x, float* __restrict__ out, int nrows) {
    extern __shared__ char smc[];
    __nv_bfloat16* Hh = reinterpret_cast<__nv_bfloat16*>(smc + OFF_H);
    __nv_bfloat16* Hl = reinterpret_cast<__nv_bfloat16*>(smc + OFF_H + 33792);
    float* scr = reinterpret_cast<float*>(smc + OFF_SCR);
    float* sbias = reinterpret_cast<float*>(smc + OFF_SB);

    const int tid = threadIdx.x;
    const int w = tid >> 5, lane = tid & 31;
    const int mg = w >> 2, ng = w & 3;       // u-GEMM: 2m x 4n warp tile
    float* wscr = scr + w * 256;
    float* hsBase = g_Hs + (size_t)blockIdx.x * (MR * 256);

    // stage a 16-row x 256-col (hi|lo) B chunk
    auto stageB = [&](const __nv_bfloat16* hi, const __nv_bfloat16* lo, int kc, int buf) {
        uint32_t dbase = (uint32_t)__cvta_generic_to_shared(smc + OFF_B + buf * 16896);
#pragma unroll
        for (int i = 0; i < 4; i++) {
            int idx = tid + i * NT;           // 0..1023
            int half = idx >> 9, e = idx & 511;
            int row = e >> 5, col = e & 31;
            const __nv_bfloat16* src = (half ? lo : hi) + (size_t)(kc * 16 + row) * 256 + col * 8;
            uint32_t dst = dbase + half * 8448 + (row * BLD + col * 8) * 2;
            CP16(dst, src);
        }
    };
    // stage a 16-row x 192-col (hi|lo) chunk (W23): 24 col-groups of 8
    auto stageBd = [&](int kc, int buf) {
        uint32_t dbase = (uint32_t)__cvta_generic_to_shared(smc + OFF_B + buf * 16896);
#pragma unroll
        for (int i = 0; i < 3; i++) {
            int idx = tid + i * NT;           // 0..767
            int half = idx >= 384, e = idx - half * 384;   // e in 0..383
            int row = e / 24, col = e - row * 24;          // 16 rows x 24 groups
            const __nv_bfloat16* src = (half ? g_W23l : g_W23h) + (size_t)(kc * 16 + row) * 192 + col * 8;
            uint32_t dst = dbase + half * 8448 + (row * BLD + col * 8) * 2;
            CP16(dst, src);
        }
    };
    // u/W231 chunk MMA: warp tile 2m x 4n, one 16-k step
    auto mmaChunk = [&](FragC* acc, int kc, int buf) {
        const __nv_bfloat16* Bh = reinterpret_cast<const __nv_bfloat16*>(smc + OFF_B + buf * 16896);
        const __nv_bfloat16* Bl = reinterpret_cast<const __nv_bfloat16*>(smc + OFF_B + buf * 16896 + 8448);
        FragA fa0h, fa0l, fa1h, fa1l;
        wmma::load_matrix_sync(fa0h, Hh + (mg * 2 + 0) * 16 * HLD + kc * 16, HLD);
        wmma::load_matrix_sync(fa0l, Hl + (mg * 2 + 0) * 16 * HLD + kc * 16, HLD);
        wmma::load_matrix_sync(fa1h, Hh + (mg * 2 + 1) * 16 * HLD + kc * 16, HLD);
        wmma::load_matrix_sync(fa1l, Hl + (mg * 2 + 1) * 16 * HLD + kc * 16, HLD);
        FragB fbh, fbl;
#pragma unroll
        for (int nj = 0; nj < 4; nj++) {
            const int n = ng * 4 + nj;
            wmma::load_matrix_sync(fbh, Bh + n * 16, BLD);
            wmma::load_matrix_sync(fbl, Bl + n * 16, BLD);
            wmma::mma_sync(acc[0 * 4 + nj], fa0h, fbh, acc[0 * 4 + nj]);
            wmma::mma_sync(acc[0 * 4 + nj], fa0h, fbl, acc[0 * 4 + nj]);
            wmma::mma_sync(acc[0 * 4 + nj], fa0l, fbh, acc[0 * 4 + nj]);
            wmma::mma_sync(acc[1 * 4 + nj], fa1h, fbh, acc[1 * 4 + nj]);
            wmma::mma_sync(acc[1 * 4 + nj], fa1h, fbl, acc[1 * 4 + nj]);
            wmma::mma_sync(acc[1 * 4 + nj], fa1l, fbh, acc[1 * 4 + nj]);
        }
    };

    for (int tile = blockIdx.x; tile < NTILE; tile += gridDim.x) {
        const int row0 = tile * MR;

        // ---- stage x split into panels + prefetch W1a chunk 0 ----
        stageB(g_W1h, g_W1l, 0, 0); CP_COMMIT();
#pragma unroll
        for (int i = 0; i < 2; i++) {
            int idx = tid + i * NT;            // 0..511
            int r = idx >> 3, c4 = idx & 7;    // 64 rows x 8 groups of 32 cols
            const float* xr = x + (size_t)(row0 + r) * 256 + c4 * 32;
#pragma unroll
            for (int q = 0; q < 8; q++) {
                float4 v = *reinterpret_cast<const float4*>(xr + q * 4);
                splitstore4(&Hh[r * HLD + c4 * 32 + q * 4], &Hl[r * HLD + c4 * 32 + q * 4], v);
            }
        }
        CP_WAIT0(); __syncthreads();

        // ---- u0 = x @ W1a ----
        FragC acc[8];
#pragma unroll
        for (int i = 0; i < 8; i++) wmma::fill_fragment(acc[i], 0.f);
        for (int kc = 0; kc < 16; kc++) {
            if (kc < 15) { stageB(g_W1h, g_W1l, kc + 1, (kc + 1) & 1); CP_COMMIT(); }
            mmaChunk(acc, kc, kc & 1);
            CP_WAIT0(); __syncthreads();
        }

        // ---- 3 iterations ----
        for (int it = 0; it < 3; it++) {
            sbias[tid] = g_cb[it * 256 + tid];
            if (it < 2) stageB(g_W231h, g_W231l, 0, 0); else stageBd(0, 0);
            CP_COMMIT();
            __syncthreads();

            // conversion: h = relu(acc + bias); Hs accumulate; panels <- h (or hsum)
#pragma unroll
            for (int mi = 0; mi < 2; mi++) {
#pragma unroll
                for (int nj = 0; nj < 4; nj++) {
                    wmma::store_matrix_sync(wscr, acc[mi * 4 + nj], 16, wmma::mem_row_major);
                    __syncwarp();
                    const int gr = (mg * 2 + mi) * 16, gc = (ng * 4 + nj) * 16;
#pragma unroll
                    for (int e = 0; e < 8; e++) {
                        int idx = lane * 8 + e;
                        int r = idx >> 4, c = idx & 15;
                        int row = gr + r, col = gc + c;
                        float h = fmaxf(wscr[r * 16 + c] + sbias[col], 0.f);
                        float* hp = hsBase + row * 256 + col;
                        if (it == 0) *hp = h;
                        else if (it == 1) *hp += h;
                        else h += *hp;
                        __nv_bfloat16 hh = __float2bfloat16(h);
                        __nv_bfloat16 hl = __float2bfloat16(h - __bfloat162float(hh));
                        Hh[row * HLD + col] = hh;
                        Hl[row * HLD + col] = hl;
                    }
                    __syncwarp();
                }
            }
            CP_WAIT0(); __syncthreads();

            if (it < 2) {
                for (int kc = 0; kc < 16; kc++) {
                    if (kc < 15) { stageB(g_W231h, g_W231l, kc + 1, (kc + 1) & 1); CP_COMMIT(); }
                    mmaChunk(acc, kc, kc & 1);
                    CP_WAIT0(); __syncthreads();
                }
            }
        }

        // ---- delta = Hsum_panels @ W23 (N=192; warp: 2m x 3n) ----
        const int mgd = w >> 2, ngd = w & 3;
        FragC dacc[6];
#pragma unroll
        for (int j = 0; j < 6; j++) wmma::fill_fragment(dacc[j], 0.f);
        for (int kc = 0; kc < 16; kc++) {
            if (kc < 15) { stageBd(kc + 1, (kc + 1) & 1); CP_COMMIT(); }
            {
                const int buf = kc & 1;
                const __nv_bfloat16* Bh = reinterpret_cast<const __nv_bfloat16*>(smc + OFF_B + buf * 16896);
                const __nv_bfloat16* Bl = reinterpret_cast<const __nv_bfloat16*>(smc + OFF_B + buf * 16896 + 8448);
                FragA fa0h, fa0l, fa1h, fa1l;
                wmma::load_matrix_sync(fa0h, Hh + (mgd * 2 + 0) * 16 * HLD + kc * 16, HLD);
                wmma::load_matrix_sync(fa0l, Hl + (mgd * 2 + 0) * 16 * HLD + kc * 16, HLD);
                wmma::load_matrix_sync(fa1h, Hh + (mgd * 2 + 1) * 16 * HLD + kc * 16, HLD);
                wmma::load_matrix_sync(fa1l, Hl + (mgd * 2 + 1) * 16 * HLD + kc * 16, HLD);
                FragB fbh, fbl;
#pragma unroll
                for (int j = 0; j < 3; j++) {
                    const int n = ngd * 3 + j;
                    wmma::load_matrix_sync(fbh, Bh + n * 16, BLD);
                    wmma::load_matrix_sync(fbl, Bl + n * 16, BLD);
                    wmma::mma_sync(dacc[0 * 3 + j], fa0h, fbh, dacc[0 * 3 + j]);
                    wmma::mma_sync(dacc[0 * 3 + j], fa0h, fbl, dacc[0 * 3 + j]);
                    wmma::mma_sync(dacc[0 * 3 + j], fa0l, fbh, dacc[0 * 3 + j]);
                    wmma::mma_sync(dacc[1 * 3 + j], fa1h, fbh, dacc[1 * 3 + j]);
                    wmma::mma_sync(dacc[1 * 3 + j], fa1h, fbl, dacc[1 * 3 + j]);
                    wmma::mma_sync(dacc[1 * 3 + j], fa1l, fbh, dacc[1 * 3 + j]);
                }
            }
            CP_WAIT0(); __syncthreads();
        }

        // ---- theta = tfin + dacc, into H region (panels dead) ----
        float* th = reinterpret_cast<float*>(smc + OFF_H);
#pragma unroll
        for (int mi = 0; mi < 2; mi++) {
#pragma unroll
            for (int j = 0; j < 3; j++) {
                const int n = ngd * 3 + j;
                if (n < 10) {
                    wmma::store_matrix_sync(wscr, dacc[mi * 3 + j], 16, wmma::mem_row_major);
                    __syncwarp();
#pragma unroll
                    for (int e = 0; e < 8; e++) {
                        int idx = lane * 8 + e;
                        int r = idx >> 4, c = idx & 15;
                        th[((mgd * 2 + mi) * 16 + r) * THLD + n * 16 + c] =
                            wscr[r * 16 + c] + g_tfin[n * 16 + c];
                    }
                    __syncwarp();
                }
            }
        }
        __syncthreads();

        // ---- epilogue: rot6d -> rotmat, betas, camera ----
        float* out_rot  = out;
        float* out_beta = out + (size_t)nrows * 216;
        float* out_cam  = out + (size_t)nrows * 226;

        for (int idx = tid; idx < MR * 24; idx += NT) {
            int r = idx / 24, g = idx - 24 * r;
            const float* tp = &th[r * THLD + g * 6];
            float a1x = tp[0], a2x = tp[1];
            float a1y = tp[2], a2y = tp[3];
            float a1z = tp[4], a2z = tp[5];
            float n1 = sqrtf(a1x * a1x + a1y * a1y + a1z * a1z);
            float i1 = 1.f / fmaxf(n1, 1e-12f);
            float b1x = a1x * i1, b1y = a1y * i1, b1z = a1z * i1;
            float d = b1x * a2x + b1y * a2y + b1z * a2z;
            float c2x = a2x - d * b1x, c2y = a2y - d * b1y, c2z = a2z - d * b1z;
            float n2 = sqrtf(c2x * c2x + c2y * c2y + c2z * c2z);
            float i2 = 1.f / fmaxf(n2, 1e-12f);
            float b2x = c2x * i2, b2y = c2y * i2, b2z = c2z * i2;
            float b3x = b1y * b2z - b1z * b2y;
            float b3y = b1z * b2x - b1x * b2z;
            float b3z = b1x * b2y - b1y * b2x;
            float* o = out_rot + (size_t)(row0 + r) * 216 + g * 9;
            o[0] = b1x; o[1] = b2x; o[2] = b3x;
            o[3] = b1y; o[4] = b2y; o[5] = b3y;
            o[6] = b1z; o[7] = b2z; o[8] = b3z;
        }
        for (int idx = tid; idx < MR * 13; idx += NT) {
            int r = idx / 13, c = idx - 13 * r;
            if (c < 10)
                out_beta[(size_t)(row0 + r) * 10 + c] = th[r * THLD + 144 + c];
            else
                out_cam[(size_t)(row0 + r) * 3 + (c - 10)] = th[r * THLD + 154 + (c - 10)];
        }
        __syncthreads();
    }
}

// ---------------- launch ----------------
extern "C" void kernel_launch(void* const* d_in, const int* in_sizes, int n_in,
                              void* d_out, int out_size) {
    const float* x    = (const float*)d_in[0];
    const float* W1   = (const float*)d_in[2];
    const float* b1   = (const float*)d_in[3];
    const float* W2   = (const float*)d_in[4];
    const float* b2   = (const float*)d_in[5];
    const float* W3   = (const float*)d_in[6];
    const float* b3   = (const float*)d_in[7];
    const float* icr  = (const float*)d_in[8];
    const float* ish  = (const float*)d_in[9];
    const float* icam = (const float*)d_in[10];
    float* out = (float*)d_out;

    int nrows = in_sizes[0] / 256;  // 115200

    prep1_k<<<514, 256>>>(W1, b1, W2, b2, W3, b3, icr, ish, icam);
    prep2_k<<<257, 256>>>(W1);

    cudaFuncSetAttribute(detr_wmma, cudaFuncAttributeMaxDynamicSharedMemorySize, SMEM_SZ);
    detr_wmma<<<NGRID, NT, SMEM_SZ>>>(x, out, nrows);
}